// round 1
// baseline (speedup 1.0000x reference)
#include <cuda_runtime.h>
#include <math.h>

#define Bb      8
#define Nn      1024
#define DIN     64
#define Hh      128
#define MSGd    128
#define Ll      5
#define TGTd    12
#define NLAYERS 3
#define BN      (Bb*Nn)

// ---------------- scratch (device globals; no runtime allocation) ----------
__device__ float d_h   [BN * Hh];            // current hidden state (4 MB)
__device__ float d_h0  [BN * Hh];            // padded input         (4 MB)
__device__ float d_mask[BN];                 // node mask
__device__ float d_Ml  [BN * Ll * MSGd];     // per-label messages   (21 MB)
__device__ float d_agg [BN * MSGd];          // aggregated messages  (4 MB)
__device__ float d_g6  [BN * 768];           // [gi | gh] GRU pre-activations (25 MB)

// ---------------- init: pad h_in -> h0, node mask --------------------------
__global__ void k_init(const float* __restrict__ h_in) {
    int row = blockIdx.x;
    int c   = threadIdx.x;          // 0..127
    float v = (c < DIN) ? h_in[row * DIN + c] : 0.f;
    d_h0[row * Hh + c] = v;
    d_h [row * Hh + c] = v;
    __shared__ float sb[128];
    sb[c] = fabsf(v);
    __syncthreads();
    for (int off = 64; off; off >>= 1) {
        if (c < off) sb[c] += sb[c + off];
        __syncthreads();
    }
    if (c == 0) d_mask[row] = (sb[0] > 0.f) ? 1.f : 0.f;
}

// ---------------- K1: Ml[b,w,l,:] = h[b,w,:] @ A[l] ------------------------
// grid (BN/64, L), 256 threads. Tile: 64 rows x 128 cols, K tiled by 16.
__global__ void k_msg(const float* __restrict__ A) {
    __shared__ float hs[64][132];     // padded: conflict-free row reads
    __shared__ float As[16][128];
    const int l   = blockIdx.y;
    const int r0  = blockIdx.x * 64;
    const int tid = threadIdx.x;

    for (int i = tid; i < 64 * 32; i += 256) {
        int v = i >> 5, c4 = i & 31;
        *(float4*)&hs[v][c4 * 4] = *(const float4*)&d_h[(r0 + v) * Hh + c4 * 4];
    }

    float acc[4][8];
#pragma unroll
    for (int i = 0; i < 4; ++i)
#pragma unroll
        for (int j = 0; j < 8; ++j) acc[i][j] = 0.f;

    const int to = (tid & 15) * 8;     // output col
    const int tw = (tid >> 4) * 4;     // output row

    for (int dt = 0; dt < Hh; dt += 16) {
        __syncthreads();
        for (int i = tid; i < 512; i += 256)
            ((float4*)As)[i] = ((const float4*)(A + (l * Hh + dt) * MSGd))[i];
        __syncthreads();
#pragma unroll
        for (int dd = 0; dd < 16; ++dd) {
            float4 a0 = *(float4*)&As[dd][to];
            float4 a1 = *(float4*)&As[dd][to + 4];
#pragma unroll
            for (int i = 0; i < 4; ++i) {
                float hv = hs[tw + i][dt + dd];
                acc[i][0] += hv * a0.x; acc[i][1] += hv * a0.y;
                acc[i][2] += hv * a0.z; acc[i][3] += hv * a0.w;
                acc[i][4] += hv * a1.x; acc[i][5] += hv * a1.y;
                acc[i][6] += hv * a1.z; acc[i][7] += hv * a1.w;
            }
        }
    }
#pragma unroll
    for (int i = 0; i < 4; ++i) {
        float4 o0 = make_float4(acc[i][0], acc[i][1], acc[i][2], acc[i][3]);
        float4 o1 = make_float4(acc[i][4], acc[i][5], acc[i][6], acc[i][7]);
        float* dst = d_Ml + (size_t)(r0 + tw + i) * (Ll * MSGd) + l * MSGd + to;
        *(float4*)dst       = o0;
        *(float4*)(dst + 4) = o1;
    }
}

// ---------------- K2: agg[b,v,:] = sum_w g[b,v,w] * Ml[b,w,e[b,v,w],:] -----
// grid (Nn/64, Bb), 512 threads. warp -> 4 v-rows, lane -> 4 output channels.
__global__ void k_agg(const float* __restrict__ g, const int* __restrict__ e) {
    __shared__ float         Mls[16 * 640];   // 40 KB: 16 w x (5 labels x 128)
    __shared__ float         gsh[64][16];     // 4 KB
    __shared__ unsigned char esh[64][16];     // 1 KB

    const int b   = blockIdx.y;
    const int v0  = blockIdx.x * 64;
    const int tid = threadIdx.x;
    const int warp = tid >> 5, lane = tid & 31;
    const int vb = warp * 4;
    const int o4 = lane * 4;

    float4 acc[4];
#pragma unroll
    for (int i = 0; i < 4; ++i) acc[i] = make_float4(0.f, 0.f, 0.f, 0.f);

    for (int wt = 0; wt < Nn; wt += 16) {
        __syncthreads();
        const float4* src = (const float4*)(d_Ml + (size_t)(b * Nn + wt) * 640);
#pragma unroll
        for (int i = 0; i < 5; ++i)
            ((float4*)Mls)[tid + i * 512] = src[tid + i * 512];

        if (tid < 256) {
            int v = tid >> 2, c = tid & 3;
            *(float4*)&gsh[v][c * 4] =
                *(const float4*)&g[(size_t)(b * Nn + v0 + v) * Nn + wt + c * 4];
        } else {
            int j = tid - 256;
            int v = j >> 2, c = j & 3;
            int4 ev = *(const int4*)&e[(size_t)(b * Nn + v0 + v) * Nn + wt + c * 4];
            unsigned int packed = (unsigned)ev.x | ((unsigned)ev.y << 8) |
                                  ((unsigned)ev.z << 16) | ((unsigned)ev.w << 24);
            *(unsigned int*)&esh[v][c * 4] = packed;
        }
        __syncthreads();

#pragma unroll
        for (int w = 0; w < 16; ++w) {
#pragma unroll
            for (int i = 0; i < 4; ++i) {
                float gv = gsh[vb + i][w];
                int   lv = esh[vb + i][w];
                const float4 mv = *(const float4*)&Mls[w * 640 + lv * MSGd + o4];
                acc[i].x += gv * mv.x;
                acc[i].y += gv * mv.y;
                acc[i].z += gv * mv.z;
                acc[i].w += gv * mv.w;
            }
        }
    }
#pragma unroll
    for (int i = 0; i < 4; ++i)
        *(float4*)&d_agg[(size_t)(b * Nn + v0 + vb + i) * MSGd + o4] = acc[i];
}

// ---------------- K3a: [gi|gh] = [agg @ Wi | h @ Wh] -----------------------
// grid (BN/64, 6), 256 threads. col blocks 0..2 -> gi, 3..5 -> gh.
__global__ void k_gemm(const float* __restrict__ Wi, const float* __restrict__ Wh) {
    __shared__ float Xs[64][33];
    __shared__ float Ws[32][128];
    const int c   = blockIdx.y;
    const int r0  = blockIdx.x * 64;
    const int tid = threadIdx.x;
    const float* X = (c < 3) ? d_agg : d_h;
    const float* W = (c < 3) ? Wi    : Wh;
    const int colbase = (c % 3) * 128;

    float acc[4][8];
#pragma unroll
    for (int i = 0; i < 4; ++i)
#pragma unroll
        for (int j = 0; j < 8; ++j) acc[i][j] = 0.f;

    const int to = (tid & 15) * 8;
    const int tw = (tid >> 4) * 4;

    for (int dt = 0; dt < 128; dt += 32) {
        __syncthreads();
        for (int i = tid; i < 64 * 32; i += 256) {
            int v = i >> 5, dd = i & 31;
            Xs[v][dd] = X[(size_t)(r0 + v) * 128 + dt + dd];
        }
        for (int i = tid; i < 32 * 32; i += 256) {
            int dd = i >> 5, j4 = i & 31;
            *(float4*)&Ws[dd][j4 * 4] =
                *(const float4*)&W[(size_t)(dt + dd) * 384 + colbase + j4 * 4];
        }
        __syncthreads();
#pragma unroll
        for (int dd = 0; dd < 32; ++dd) {
            float4 w0 = *(float4*)&Ws[dd][to];
            float4 w1 = *(float4*)&Ws[dd][to + 4];
#pragma unroll
            for (int i = 0; i < 4; ++i) {
                float x = Xs[tw + i][dd];
                acc[i][0] += x * w0.x; acc[i][1] += x * w0.y;
                acc[i][2] += x * w0.z; acc[i][3] += x * w0.w;
                acc[i][4] += x * w1.x; acc[i][5] += x * w1.y;
                acc[i][6] += x * w1.z; acc[i][7] += x * w1.w;
            }
        }
    }
#pragma unroll
    for (int i = 0; i < 4; ++i) {
        float* dst = d_g6 + (size_t)(r0 + tw + i) * 768 + c * 128 + to;
        *(float4*)dst       = make_float4(acc[i][0], acc[i][1], acc[i][2], acc[i][3]);
        *(float4*)(dst + 4) = make_float4(acc[i][4], acc[i][5], acc[i][6], acc[i][7]);
    }
}

// ---------------- K3b: GRU gates + state update ----------------------------
__global__ void k_gru(const float* __restrict__ bi, const float* __restrict__ bh) {
    const int row = blockIdx.x;
    const int c   = threadIdx.x;  // 0..127
    const float* gr = d_g6 + (size_t)row * 768;
    float ir = gr[c]       + bi[c];
    float iz = gr[128 + c] + bi[128 + c];
    float in_= gr[256 + c] + bi[256 + c];
    float hr = gr[384 + c] + bh[c];
    float hz = gr[512 + c] + bh[128 + c];
    float hn = gr[640 + c] + bh[256 + c];
    float r = 1.f / (1.f + __expf(-(ir + hr)));
    float z = 1.f / (1.f + __expf(-(iz + hz)));
    float n = tanhf(in_ + r * hn);
    float hold = d_h[(size_t)row * 128 + c];
    d_h[(size_t)row * 128 + c] = ((1.f - z) * n + z * hold) * d_mask[row];
}

// ---------------- readout: deterministic per-batch reduce ------------------
// grid 8, 1024 threads: thread = node.
__global__ void k_read(const float* __restrict__ Wg, const float* __restrict__ bg,
                       const float* __restrict__ Wo, const float* __restrict__ bo,
                       float* __restrict__ out) {
    __shared__ float Wgs[256 * 12];
    __shared__ float Wos[128 * 12];
    __shared__ float part[32][12];
    const int tid = threadIdx.x;
    const int b   = blockIdx.x;
    for (int i = tid; i < 256 * 12; i += 1024) Wgs[i] = Wg[i];
    for (int i = tid; i < 128 * 12; i += 1024) Wos[i] = Wo[i];
    __syncthreads();

    const int row = b * Nn + tid;
    float ga[12], oa[12];
#pragma unroll
    for (int t = 0; t < 12; ++t) { ga[t] = 0.f; oa[t] = 0.f; }
    float sm = 0.f;
    const float* hT  = d_h  + (size_t)row * 128;
    const float* h0p = d_h0 + (size_t)row * 128;
#pragma unroll 4
    for (int d = 0; d < 128; ++d) {
        float x = hT[d];
#pragma unroll
        for (int t = 0; t < 12; ++t) {
            ga[t] += x * Wgs[d * 12 + t];
            oa[t] += x * Wos[d * 12 + t];
        }
    }
#pragma unroll 4
    for (int d = 0; d < 128; ++d) {
        float x0 = h0p[d];
        sm += x0;
#pragma unroll
        for (int t = 0; t < 12; ++t) ga[t] += x0 * Wgs[(128 + d) * 12 + t];
    }
    const float m = (sm > 0.f) ? 1.f : 0.f;
    const int lane = tid & 31, warp = tid >> 5;
#pragma unroll
    for (int t = 0; t < 12; ++t) {
        float val = (1.f / (1.f + __expf(-(ga[t] + bg[t])))) * (oa[t] + bo[t]) * m;
        for (int off = 16; off; off >>= 1)
            val += __shfl_down_sync(0xffffffffu, val, off);
        if (lane == 0) part[warp][t] = val;
    }
    __syncthreads();
    if (tid < 12) {
        float s = 0.f;
        for (int w = 0; w < 32; ++w) s += part[w][tid];
        out[b * 12 + tid] = s;
    }
}

// ---------------- launch ---------------------------------------------------
extern "C" void kernel_launch(void* const* d_in, const int* in_sizes, int n_in,
                              void* d_out, int out_size) {
    const float* g    = (const float*)d_in[0];
    const float* h_in = (const float*)d_in[1];
    const int*   e    = (const int*)  d_in[2];
    const float* A    = (const float*)d_in[3];
    const float* Wi   = (const float*)d_in[4];
    const float* Wh   = (const float*)d_in[5];
    const float* bi   = (const float*)d_in[6];
    const float* bh   = (const float*)d_in[7];
    const float* Wg   = (const float*)d_in[8];
    const float* bg   = (const float*)d_in[9];
    const float* Wo   = (const float*)d_in[10];
    const float* bo   = (const float*)d_in[11];
    float* out = (float*)d_out;

    k_init<<<BN, 128>>>(h_in);
    for (int layer = 0; layer < NLAYERS; ++layer) {
        k_msg <<<dim3(BN / 64, Ll), 256>>>(A);
        k_agg <<<dim3(Nn / 64, Bb), 512>>>(g, e);
        k_gemm<<<dim3(BN / 64, 6),  256>>>(Wi, Wh);
        k_gru <<<BN, 128>>>(bi, bh);
    }
    k_read<<<Bb, 1024>>>(Wg, bg, Wo, bo, out);
}

// round 5
// speedup vs baseline: 1.3595x; 1.3595x over previous
#include <cuda_runtime.h>
#include <math.h>
#include <stdint.h>

#define Bb      8
#define Nn      1024
#define DIN     64
#define Hh      128
#define Ll      5
#define TGTd    12
#define NL      3
#define BN      (Bb*Nn)

// ---------------- device scratch (statics; no runtime allocation) ----------
__device__ float    d_h   [BN*Hh];
__device__ float    d_h0  [BN*Hh];
__device__ float    d_mask[BN];
__device__ float    d_Ml  [BN*Ll*Hh];       // [b,w,l,o]  21 MB
__device__ float    d_agg [BN*Hh];
__device__ float    d_g6  [BN*768];
__device__ uint32_t d_gep [(size_t)BN*Nn];  // g with label packed in low 3 bits (33.5 MB)
__device__ float    d_Acat[Hh*Ll*Hh];       // [d, l*128+o]

__device__ __forceinline__ float tf32r(float x) {
    uint32_t u;
    asm("cvt.rna.tf32.f32 %0, %1;" : "=r"(u) : "f"(x));
    return __uint_as_float(u);
}

// ---------------- init: pad h_in -> h0, node mask (full fp32) --------------
__global__ void k_init(const float* __restrict__ h_in) {
    int row = blockIdx.x;
    int c   = threadIdx.x;          // 0..127
    float v = (c < DIN) ? h_in[row * DIN + c] : 0.f;
    d_h0[row * Hh + c] = v;
    d_h [row * Hh + c] = v;
    __shared__ float sb[128];
    sb[c] = fabsf(v);
    __syncthreads();
    for (int off = 64; off; off >>= 1) {
        if (c < off) sb[c] += sb[c + off];
        __syncthreads();
    }
    if (c == 0) d_mask[row] = (sb[0] > 0.f) ? 1.f : 0.f;
}

// ---------------- pack g + label into one u32 (layer-invariant) ------------
__global__ void k_gepack(const float* __restrict__ g, const int* __restrict__ e) {
    size_t i = (size_t)blockIdx.x * 256 + threadIdx.x;
    if (i >= (size_t)BN * Nn) return;
    uint32_t gb = __float_as_uint(g[i]) & 0xFFFFFFF8u;   // clear low 3 mantissa bits
    d_gep[i] = gb | (uint32_t)(e[i] & 7);                // label in [0,5)
}

// ---------------- repack A -> Acat[d][l*128+o] (fp32, no rounding) ---------
__global__ void k_repack(const float* __restrict__ A) {
    int i = blockIdx.x * 256 + threadIdx.x;
    if (i < Hh * Ll * Hh) {
        int o = i % Hh;
        int d = (i / Hh) % Hh;
        int l = i / (Hh * Hh);
        d_Acat[d * (Ll * Hh) + l * Hh + o] = A[((size_t)l * Hh + d) * Hh + o];
    }
}

// ============================================================================
// 3xTF32 tensor-core GEMM: C[MxN] = A[MxK] @ B[KxN], fp32 in/out, fp32-grade
// accuracy via hi/lo tf32 split (acc = lo*hi + hi*lo + hi*hi).
// Block tile 64(M) x 128(N), K-tile 32, 256 threads, cp.async double-buffered.
// ============================================================================
#define ASZ (64*36)
#define BSZ (32*132)
#define SMEM_MMA ((2*ASZ + 2*BSZ) * 4)

#define CP16(dst, src) asm volatile("cp.async.cg.shared.global [%0], [%1], 16;\n" :: "r"(dst), "l"(src))
#define CPCOMMIT()     asm volatile("cp.async.commit_group;\n")
#define CPWAIT0()      asm volatile("cp.async.wait_group 0;\n")

#define MMA8(c, a, b) \
    asm volatile("mma.sync.aligned.m16n8k8.row.col.f32.tf32.tf32.f32 " \
        "{%0,%1,%2,%3},{%4,%5,%6,%7},{%8,%9},{%0,%1,%2,%3};" \
        : "+f"(c[0]), "+f"(c[1]), "+f"(c[2]), "+f"(c[3]) \
        : "r"(a[0]), "r"(a[1]), "r"(a[2]), "r"(a[3]), "r"(b[0]), "r"(b[1]))

__device__ __forceinline__ void split_tf32(float x, uint32_t& hi, uint32_t& lo) {
    float h = tf32r(x);
    float l = tf32r(x - h);
    hi = __float_as_uint(h);
    lo = __float_as_uint(l);
}

__global__ __launch_bounds__(256) void k_mma3(
    const float* __restrict__ A, int lda,
    const float* __restrict__ B, int ldb,
    float* __restrict__ C, int ldc,
    int K)
{
    extern __shared__ float sm[];
    float* As = sm;                   // [2][64][36]
    float* Bs = sm + 2 * ASZ;         // [2][32][132]
    const uint32_t aBase = (uint32_t)__cvta_generic_to_shared(As);
    const uint32_t bBase = (uint32_t)__cvta_generic_to_shared(Bs);

    const int tid  = threadIdx.x;
    const int wid  = tid >> 5, lane = tid & 31;
    const int m0   = blockIdx.y * 64;
    const int n0   = blockIdx.x * 128;
    const int wm   = (wid >> 2) * 32;
    const int wn   = (wid & 3) * 32;

    const float* Ab = A + (size_t)m0 * lda;
    const float* Bp = B + n0;
    const int am = tid >> 3,  ak4 = tid & 7;
    const int bk = tid >> 5,  bn4 = tid & 31;

    float acc[2][4][4];
#pragma unroll
    for (int mt = 0; mt < 2; ++mt)
#pragma unroll
        for (int nt = 0; nt < 4; ++nt)
#pragma unroll
            for (int i = 0; i < 4; ++i) acc[mt][nt][i] = 0.f;

    const int T = K >> 5;

    {   // preload tile 0
#pragma unroll
        for (int r = 0; r < 2; ++r) {
            int m = am + r * 32;
            CP16(aBase + (uint32_t)((m * 36 + ak4 * 4) * 4),
                 Ab + (size_t)m * lda + ak4 * 4);
        }
#pragma unroll
        for (int r = 0; r < 4; ++r) {
            int k = bk + r * 8;
            CP16(bBase + (uint32_t)((k * 132 + bn4 * 4) * 4),
                 Bp + (size_t)k * ldb + bn4 * 4);
        }
        CPCOMMIT();
    }

    for (int t = 0; t < T; ++t) {
        CPWAIT0();
        __syncthreads();

        if (t + 1 < T) {
            const int kt  = (t + 1) << 5;
            const int buf = (t + 1) & 1;
            const uint32_t aOff = aBase + (uint32_t)(buf * ASZ * 4);
            const uint32_t bOff = bBase + (uint32_t)(buf * BSZ * 4);
#pragma unroll
            for (int r = 0; r < 2; ++r) {
                int m = am + r * 32;
                CP16(aOff + (uint32_t)((m * 36 + ak4 * 4) * 4),
                     Ab + (size_t)m * lda + kt + ak4 * 4);
            }
#pragma unroll
            for (int r = 0; r < 4; ++r) {
                int k = bk + r * 8;
                CP16(bOff + (uint32_t)((k * 132 + bn4 * 4) * 4),
                     Bp + (size_t)(kt + k) * ldb + bn4 * 4);
            }
            CPCOMMIT();
        }

        const float* Asb = As + (t & 1) * ASZ;
        const float* Bsb = Bs + (t & 1) * BSZ;

#pragma unroll
        for (int kk = 0; kk < 32; kk += 8) {
            uint32_t afh[2][4], afl[2][4], bfh[4][2], bfl[4][2];
#pragma unroll
            for (int mt = 0; mt < 2; ++mt) {
                int r = wm + mt * 16 + (lane >> 2);
                int c = kk + (lane & 3);
                split_tf32(Asb[r * 36 + c],           afh[mt][0], afl[mt][0]);
                split_tf32(Asb[(r + 8) * 36 + c],     afh[mt][1], afl[mt][1]);
                split_tf32(Asb[r * 36 + c + 4],       afh[mt][2], afl[mt][2]);
                split_tf32(Asb[(r + 8) * 36 + c + 4], afh[mt][3], afl[mt][3]);
            }
#pragma unroll
            for (int nt = 0; nt < 4; ++nt) {
                int c = wn + nt * 8 + (lane >> 2);
                int r = kk + (lane & 3);
                split_tf32(Bsb[r * 132 + c],       bfh[nt][0], bfl[nt][0]);
                split_tf32(Bsb[(r + 4) * 132 + c], bfh[nt][1], bfl[nt][1]);
            }
#pragma unroll
            for (int mt = 0; mt < 2; ++mt)
#pragma unroll
                for (int nt = 0; nt < 4; ++nt) {
                    MMA8(acc[mt][nt], afl[mt], bfh[nt]);
                    MMA8(acc[mt][nt], afh[mt], bfl[nt]);
                    MMA8(acc[mt][nt], afh[mt], bfh[nt]);
                }
        }
    }

#pragma unroll
    for (int mt = 0; mt < 2; ++mt) {
        int row = m0 + wm + mt * 16 + (lane >> 2);
#pragma unroll
        for (int nt = 0; nt < 4; ++nt) {
            int col = n0 + wn + nt * 8 + 2 * (lane & 3);
            *(float2*)&C[(size_t)row * ldc + col] =
                make_float2(acc[mt][nt][0], acc[mt][nt][1]);
            *(float2*)&C[(size_t)(row + 8) * ldc + col] =
                make_float2(acc[mt][nt][2], acc[mt][nt][3]);
        }
    }
}

// ============================================================================
// Exact fp32 label-gather aggregation, cp.async double-buffered.
// agg[b,v,:] = sum_w g[b,v,w] * Ml[b,w,e[b,v,w],:]
// grid (Nn/64, Bb), 512 threads: warp -> 4 v rows, lane -> 4 channels.
// ============================================================================
#define AGG_SMEM ((2*16*640 + 2*64*16) * 4)   // 88 KB

__global__ __launch_bounds__(512) void k_agg() {
    extern __shared__ float asm_[];
    float*    Mls = asm_;                       // [2][16][640]
    uint32_t* ges = (uint32_t*)(asm_ + 2 * 16 * 640);  // [2][64][16]
    const uint32_t mBase = (uint32_t)__cvta_generic_to_shared(Mls);
    const uint32_t gBase = (uint32_t)__cvta_generic_to_shared(ges);

    const int b   = blockIdx.y;
    const int v0  = blockIdx.x * 64;
    const int tid = threadIdx.x;
    const int warp = tid >> 5, lane = tid & 31;
    const int vb = warp * 4;
    const int o4 = lane * 4;

    const float*    Msrc = d_Ml + (size_t)b * Nn * 640;
    const uint32_t* Gsrc = d_gep + ((size_t)b * Nn + v0) * Nn;

    float4 acc[4];
#pragma unroll
    for (int i = 0; i < 4; ++i) acc[i] = make_float4(0.f, 0.f, 0.f, 0.f);

    {   // preload tile 0 (wt = 0)
#pragma unroll
        for (int r = 0; r < 5; ++r) {
            int idx = r * 512 + tid;            // float4 index into 16*640
            CP16(mBase + (uint32_t)(idx * 16), Msrc + idx * 4);
        }
        if (tid < 256) {
            int v = tid >> 2, c = tid & 3;
            CP16(gBase + (uint32_t)((v * 16 + c * 4) * 4),
                 Gsrc + (size_t)v * Nn + c * 4);
        }
        CPCOMMIT();
    }

    for (int t = 0; t < Nn / 16; ++t) {
        CPWAIT0();
        __syncthreads();

        if (t + 1 < Nn / 16) {
            const int wt  = (t + 1) * 16;
            const int buf = (t + 1) & 1;
            const uint32_t mOff = mBase + (uint32_t)(buf * 16 * 640 * 4);
            const uint32_t gOff = gBase + (uint32_t)(buf * 64 * 16 * 4);
#pragma unroll
            for (int r = 0; r < 5; ++r) {
                int idx = r * 512 + tid;
                CP16(mOff + (uint32_t)(idx * 16), Msrc + (size_t)wt * 640 + idx * 4);
            }
            if (tid < 256) {
                int v = tid >> 2, c = tid & 3;
                CP16(gOff + (uint32_t)((v * 16 + c * 4) * 4),
                     Gsrc + (size_t)v * Nn + wt + c * 4);
            }
            CPCOMMIT();
        }

        const float*    M = Mls + (t & 1) * 16 * 640;
        const uint32_t* G = ges + (t & 1) * 64 * 16;

#pragma unroll
        for (int w = 0; w < 16; ++w) {
#pragma unroll
            for (int i = 0; i < 4; ++i) {
                uint32_t bits = G[(vb + i) * 16 + w];
                int   lv = bits & 7;
                float gv = __uint_as_float(bits);
                const float4 mv = *(const float4*)&M[w * 640 + lv * 128 + o4];
                acc[i].x += gv * mv.x;
                acc[i].y += gv * mv.y;
                acc[i].z += gv * mv.z;
                acc[i].w += gv * mv.w;
            }
        }
    }
#pragma unroll
    for (int i = 0; i < 4; ++i)
        *(float4*)&d_agg[(size_t)(b * Nn + v0 + vb + i) * Hh + o4] = acc[i];
}

// ---------------- GRU gates + state update (full fp32) ---------------------
__global__ void k_gru(const float* __restrict__ bi, const float* __restrict__ bh) {
    const int row = blockIdx.x;
    const int c   = threadIdx.x;  // 0..127
    const float* gr = d_g6 + (size_t)row * 768;
    float ir = gr[c]       + bi[c];
    float iz = gr[128 + c] + bi[128 + c];
    float in_= gr[256 + c] + bi[256 + c];
    float hr = gr[384 + c] + bh[c];
    float hz = gr[512 + c] + bh[128 + c];
    float hn = gr[640 + c] + bh[256 + c];
    float r = 1.f / (1.f + __expf(-(ir + hr)));
    float z = 1.f / (1.f + __expf(-(iz + hz)));
    float n = tanhf(in_ + r * hn);
    float hold = d_h[(size_t)row * 128 + c];
    d_h[(size_t)row * 128 + c] = ((1.f - z) * n + z * hold) * d_mask[row];
}

// ---------------- readout: deterministic per-batch reduce ------------------
__global__ void k_read(const float* __restrict__ Wg, const float* __restrict__ bg,
                       const float* __restrict__ Wo, const float* __restrict__ bo,
                       float* __restrict__ out) {
    __shared__ float Wgs[256 * 12];
    __shared__ float Wos[128 * 12];
    __shared__ float part[32][12];
    const int tid = threadIdx.x;
    const int b   = blockIdx.x;
    for (int i = tid; i < 256 * 12; i += 1024) Wgs[i] = Wg[i];
    for (int i = tid; i < 128 * 12; i += 1024) Wos[i] = Wo[i];
    __syncthreads();

    const int row = b * Nn + tid;
    float ga[12], oa[12];
#pragma unroll
    for (int t = 0; t < 12; ++t) { ga[t] = 0.f; oa[t] = 0.f; }
    float sm0 = 0.f;
    const float* hT  = d_h  + (size_t)row * 128;
    const float* h0p = d_h0 + (size_t)row * 128;
#pragma unroll 4
    for (int d = 0; d < 128; ++d) {
        float x = hT[d];
#pragma unroll
        for (int t = 0; t < 12; ++t) {
            ga[t] += x * Wgs[d * 12 + t];
            oa[t] += x * Wos[d * 12 + t];
        }
    }
#pragma unroll 4
    for (int d = 0; d < 128; ++d) {
        float x0 = h0p[d];
        sm0 += x0;
#pragma unroll
        for (int t = 0; t < 12; ++t) ga[t] += x0 * Wgs[(128 + d) * 12 + t];
    }
    const float m = (sm0 > 0.f) ? 1.f : 0.f;
    const int lane = tid & 31, warp = tid >> 5;
#pragma unroll
    for (int t = 0; t < 12; ++t) {
        float val = (1.f / (1.f + __expf(-(ga[t] + bg[t])))) * (oa[t] + bo[t]) * m;
        for (int off = 16; off; off >>= 1)
            val += __shfl_down_sync(0xffffffffu, val, off);
        if (lane == 0) part[warp][t] = val;
    }
    __syncthreads();
    if (tid < 12) {
        float s = 0.f;
        for (int w = 0; w < 32; ++w) s += part[w][tid];
        out[b * 12 + tid] = s;
    }
}

// ---------------- launch ---------------------------------------------------
extern "C" void kernel_launch(void* const* d_in, const int* in_sizes, int n_in,
                              void* d_out, int out_size) {
    const float* g    = (const float*)d_in[0];
    const float* h_in = (const float*)d_in[1];
    const int*   e    = (const int*)  d_in[2];
    const float* A    = (const float*)d_in[3];
    const float* Wi   = (const float*)d_in[4];
    const float* Wh   = (const float*)d_in[5];
    const float* bi   = (const float*)d_in[6];
    const float* bh   = (const float*)d_in[7];
    const float* Wg   = (const float*)d_in[8];
    const float* bg   = (const float*)d_in[9];
    const float* Wo   = (const float*)d_in[10];
    const float* bo   = (const float*)d_in[11];
    float* out = (float*)d_out;

    float *p_h, *p_Ml, *p_agg, *p_g6, *p_Acat;
    cudaGetSymbolAddress((void**)&p_h,    d_h);
    cudaGetSymbolAddress((void**)&p_Ml,   d_Ml);
    cudaGetSymbolAddress((void**)&p_agg,  d_agg);
    cudaGetSymbolAddress((void**)&p_g6,   d_g6);
    cudaGetSymbolAddress((void**)&p_Acat, d_Acat);

    cudaFuncSetAttribute(k_mma3, cudaFuncAttributeMaxDynamicSharedMemorySize, SMEM_MMA);
    cudaFuncSetAttribute(k_agg,  cudaFuncAttributeMaxDynamicSharedMemorySize, AGG_SMEM);

    k_init  <<<BN, 128>>>(h_in);
    k_gepack<<<(int)(((size_t)BN * Nn + 255) / 256), 256>>>(g, e);
    k_repack<<<(Hh*Ll*Hh + 255)/256, 256>>>(A);

    for (int layer = 0; layer < NL; ++layer) {
        // G1: Ml[8192 x 640] = h @ Acat
        k_mma3<<<dim3(5, BN/64), 256, SMEM_MMA>>>(p_h, Hh, p_Acat, Ll*Hh, p_Ml, Ll*Hh, Hh);
        // exact gather aggregation
        k_agg <<<dim3(Nn/64, Bb), 512, AGG_SMEM>>>();
        // G3a: g6[:, 0:384] = agg @ Wi
        k_mma3<<<dim3(3, BN/64), 256, SMEM_MMA>>>(p_agg, Hh, Wi, 384, p_g6, 768, Hh);
        // G3b: g6[:, 384:768] = h @ Wh
        k_mma3<<<dim3(3, BN/64), 256, SMEM_MMA>>>(p_h, Hh, Wh, 384, p_g6 + 384, 768, Hh);
        k_gru <<<BN, 128>>>(bi, bh);
    }
    k_read<<<Bb, 1024>>>(Wg, bg, Wo, bo, out);
}